// round 9
// baseline (speedup 1.0000x reference)
#include <cuda_runtime.h>
#include <cuda_fp16.h>
#include <cstdint>

#define HIDDEN   512
#define HEADS    8
#define HEAD_DIM 64
#define BATCH    4096
#define SEQ      16
#define NTOK     (BATCH * SEQ)   // 65536
#define NQKV     (3 * HIDDEN)    // 1536

// ---- scratch (no allocs allowed; device globals are the sanctioned path) ----
__device__ __half g_xh  [(size_t)NTOK * HIDDEN];   // 64 MiB  fp16 input
__device__ __half g_wq  [(size_t)NQKV * HIDDEN];   // 1.5 MiB fp16 w_qkv
__device__ __half g_wo  [(size_t)HIDDEN * HIDDEN]; // 0.5 MiB fp16 w_o
__device__ __half g_qkvh[(size_t)NTOK * NQKV];     // 192 MiB fp16 qkv
__device__ __half g_attn[(size_t)NTOK * HIDDEN];   // 64 MiB  fp16 attn out

// ---------------------------------------------------------------------------
// PTX helpers
// ---------------------------------------------------------------------------
__device__ __forceinline__ void cp_async16(void* smem, const void* gmem) {
    unsigned int s = (unsigned int)__cvta_generic_to_shared(smem);
    asm volatile("cp.async.cg.shared.global [%0], [%1], 16;\n" :: "r"(s), "l"(gmem));
}
__device__ __forceinline__ void cp_commit() {
    asm volatile("cp.async.commit_group;\n" ::: "memory");
}
template <int N>
__device__ __forceinline__ void cp_wait() {
    asm volatile("cp.async.wait_group %0;\n" :: "n"(N) : "memory");
}
__device__ __forceinline__ void ldmatrix_x4(unsigned& r0, unsigned& r1,
                                            unsigned& r2, unsigned& r3,
                                            const void* smem_ptr) {
    unsigned a = (unsigned)__cvta_generic_to_shared(smem_ptr);
    asm volatile("ldmatrix.sync.aligned.m8n8.x4.shared.b16 {%0,%1,%2,%3}, [%4];"
                 : "=r"(r0), "=r"(r1), "=r"(r2), "=r"(r3) : "r"(a));
}
__device__ __forceinline__ void mma16816(float* d, const unsigned* a,
                                         const unsigned* b) {
    asm volatile(
        "mma.sync.aligned.m16n8k16.row.col.f32.f16.f16.f32 "
        "{%0,%1,%2,%3}, {%4,%5,%6,%7}, {%8,%9}, {%0,%1,%2,%3};"
        : "+f"(d[0]), "+f"(d[1]), "+f"(d[2]), "+f"(d[3])
        : "r"(a[0]), "r"(a[1]), "r"(a[2]), "r"(a[3]), "r"(b[0]), "r"(b[1]));
}

// ---------------------------------------------------------------------------
// fp32 -> fp16 converters (n always multiple of 4)
// ---------------------------------------------------------------------------
__device__ __forceinline__ void f2h_body(const float* __restrict__ in,
                                         __half* __restrict__ out, int n) {
    int i = 4 * (blockIdx.x * blockDim.x + threadIdx.x);
    if (i < n) {
        float4 v = *reinterpret_cast<const float4*>(in + i);
        *reinterpret_cast<__half2*>(out + i)     = __floats2half2_rn(v.x, v.y);
        *reinterpret_cast<__half2*>(out + i + 2) = __floats2half2_rn(v.z, v.w);
    }
}
__global__ void f2h_x_kernel (const float* __restrict__ in) { f2h_body(in, g_xh, NTOK * HIDDEN); }
__global__ void f2h_wq_kernel(const float* __restrict__ in) { f2h_body(in, g_wq, NQKV * HIDDEN); }
__global__ void f2h_wo_kernel(const float* __restrict__ in) { f2h_body(in, g_wo, HIDDEN * HIDDEN); }

// ---------------------------------------------------------------------------
// GEMM: C[M,N] = A[M,K] * B[N,K]^T   (A,B fp16 K-contiguous; fp32 accum)
// CTA tile 128x128x32, 128 threads = 4 warps, warp tile 64x64 (2x2 grid).
// Raw mma.sync.m16n8k16 + ldmatrix.x4; all 16 ldmatrix of a stage issued
// back-to-back, then 64 independent MMAs. 2-stage cp.async double buffering
// (proven R7 skeleton: loader / sync structure / static smem unchanged).
// ---------------------------------------------------------------------------
template <bool HALF_OUT>
__device__ __forceinline__ void gemm_body(const __half* __restrict__ A,
                                          const __half* __restrict__ B,
                                          __half* __restrict__ Ch,
                                          float* __restrict__ Cf,
                                          int N, int K) {
    constexpr int BM = 128, BN = 128, BK = 32, LDS = BK + 8; // 40 halves = 80B rows
    __shared__ __align__(16) __half As[2][BM * LDS];
    __shared__ __align__(16) __half Bs[2][BN * LDS];

    const int bm   = blockIdx.y * BM;
    const int bn   = blockIdx.x * BN;
    const int tid  = threadIdx.x;
    const int warp = tid >> 5;
    const int lane = tid & 31;
    const int wm   = (warp & 1) * 64;    // warp row offset in tile
    const int wn   = (warp >> 1) * 64;   // warp col offset in tile

    // stage loader: 128x32 halves of A and B = 512 int4 each, 4/thread each
    auto stage_load = [&](int kt, int buf) {
        #pragma unroll
        for (int l = 0; l < 4; l++) {
            int v  = tid + l * 128;
            int r  = v >> 2;
            int c8 = (v & 3) * 8;
            cp_async16(&As[buf][r * LDS + c8], &A[(size_t)(bm + r) * K + kt + c8]);
            cp_async16(&Bs[buf][r * LDS + c8], &B[(size_t)(bn + r) * K + kt + c8]);
        }
        cp_commit();
    };

    // ldmatrix row/col select for this lane (same formula for A and B):
    // matrix row index = lane&15, k-half select = lane>>4
    const int lrow = lane & 15;
    const int lksel = (lane >> 4) * 8;

    float acc[4][8][4];   // [m16 block][n8 block][c0..c3]
    #pragma unroll
    for (int i = 0; i < 4; i++)
        #pragma unroll
        for (int j = 0; j < 8; j++)
            #pragma unroll
            for (int e = 0; e < 4; e++) acc[i][j][e] = 0.0f;

    const int nst = K / BK;
    stage_load(0, 0);

    for (int s = 0; s < nst; s++) {
        cp_wait<0>();
        __syncthreads();               // stage s visible to all warps
        if (s + 1 < nst) stage_load((s + 1) * BK, (s + 1) & 1);  // overlaps MMA

        const __half* as = As[s & 1];
        const __half* bs = Bs[s & 1];

        unsigned af[2][4][4];   // [kk half][m16 block][4 regs]
        unsigned bf[2][8][2];   // [kk half][n8 block][2 regs]

        // ---- issue ALL fragment loads for both kk halves back-to-back ----
        #pragma unroll
        for (int h = 0; h < 2; h++) {
            const int kk = h * 16;
            #pragma unroll
            for (int i = 0; i < 4; i++)
                ldmatrix_x4(af[h][i][0], af[h][i][1], af[h][i][2], af[h][i][3],
                            &as[(wm + i * 16 + lrow) * LDS + kk + lksel]);
            #pragma unroll
            for (int j2 = 0; j2 < 4; j2++) {
                unsigned r0, r1, r2, r3;
                ldmatrix_x4(r0, r1, r2, r3,
                            &bs[(wn + j2 * 16 + lrow) * LDS + kk + lksel]);
                bf[h][j2 * 2 + 0][0] = r0;  // n-block lo, k lo
                bf[h][j2 * 2 + 1][0] = r1;  // n-block hi, k lo
                bf[h][j2 * 2 + 0][1] = r2;  // n-block lo, k hi
                bf[h][j2 * 2 + 1][1] = r3;  // n-block hi, k hi
            }
        }

        // ---- 64 independent MMAs ----
        #pragma unroll
        for (int h = 0; h < 2; h++)
            #pragma unroll
            for (int i = 0; i < 4; i++)
                #pragma unroll
                for (int j = 0; j < 8; j++)
                    mma16816(acc[i][j], af[h][i], bf[h][j]);
    }

    // ---- epilogue: direct fragment stores ----
    const int g = lane >> 2;          // row within m16 block (0..7)
    const int c = (lane & 3) * 2;     // col pair within n8 block
    #pragma unroll
    for (int i = 0; i < 4; i++) {
        #pragma unroll
        for (int j = 0; j < 8; j++) {
            const size_t r0 = (size_t)(bm + wm + i * 16 + g);
            const size_t col = (size_t)(bn + wn + j * 8 + c);
            if (HALF_OUT) {
                *reinterpret_cast<__half2*>(&Ch[r0 * N + col]) =
                    __floats2half2_rn(acc[i][j][0], acc[i][j][1]);
                *reinterpret_cast<__half2*>(&Ch[(r0 + 8) * N + col]) =
                    __floats2half2_rn(acc[i][j][2], acc[i][j][3]);
            } else {
                *reinterpret_cast<float2*>(&Cf[r0 * N + col]) =
                    make_float2(acc[i][j][0], acc[i][j][1]);
                *reinterpret_cast<float2*>(&Cf[(r0 + 8) * N + col]) =
                    make_float2(acc[i][j][2], acc[i][j][3]);
            }
        }
    }
}

__global__ __launch_bounds__(128) void gemm_qkv_kernel() {
    gemm_body<true>(g_xh, g_wq, g_qkvh, nullptr, NQKV, HIDDEN);
}
__global__ __launch_bounds__(128) void gemm_out_kernel(float* __restrict__ C) {
    gemm_body<false>(g_attn, g_wo, nullptr, C, HIDDEN, HIDDEN);
}

// ---------------------------------------------------------------------------
// Attention: one block per (batch, head). fp16 qkv in, exact fp32 softmax,
// fp16 attn out in [token, h*64+d] layout.
// ---------------------------------------------------------------------------
__global__ __launch_bounds__(128) void attn_kernel() {
    const int b = blockIdx.x >> 3;
    const int h = blockIdx.x & 7;
    const size_t base = (size_t)b * SEQ;
    const int tid = threadIdx.x;

    __shared__ float sq[SEQ][68], sk[SEQ][68], sv[SEQ][68];
    __shared__ float sp[SEQ][SEQ + 1];

    #pragma unroll
    for (int l = 0; l < 3; l++) {
        int s  = tid >> 3;
        int d8 = (tid & 7) * 8;
        int4 raw = *reinterpret_cast<const int4*>(
            &g_qkvh[(base + s) * NQKV + l * HIDDEN + h * HEAD_DIM + d8]);
        const __half2* hp = reinterpret_cast<const __half2*>(&raw);
        float* dst = (l == 0) ? &sq[s][d8] : (l == 1) ? &sk[s][d8] : &sv[s][d8];
        #pragma unroll
        for (int p = 0; p < 4; p++) {
            float2 f = __half22float2(hp[p]);
            dst[2 * p]     = f.x;
            dst[2 * p + 1] = f.y;
        }
    }
    __syncthreads();

    #pragma unroll
    for (int l = 0; l < 2; l++) {
        int sidx = tid + l * 128;
        int i = sidx >> 4, j = sidx & 15;
        float a = 0.f;
        #pragma unroll
        for (int d = 0; d < HEAD_DIM; d++) a += sq[i][d] * sk[j][d];
        sp[i][j] = a * 0.125f;
    }
    __syncthreads();

    if (tid < SEQ) {
        float m = sp[tid][0];
        #pragma unroll
        for (int j = 1; j < SEQ; j++) m = fmaxf(m, sp[tid][j]);
        float e[SEQ], s = 0.f;
        #pragma unroll
        for (int j = 0; j < SEQ; j++) { e[j] = expf(sp[tid][j] - m); s += e[j]; }
        float inv = 1.0f / s;
        #pragma unroll
        for (int j = 0; j < SEQ; j++) sp[tid][j] = e[j] * inv;
    }
    __syncthreads();

    #pragma unroll
    for (int l = 0; l < 4; l++) {
        int o  = tid + l * 128;
        int i  = o >> 5;
        int d2 = (o & 31) * 2;
        float a0 = 0.f, a1 = 0.f;
        #pragma unroll
        for (int j = 0; j < SEQ; j++) {
            float p = sp[i][j];
            a0 += p * sv[j][d2];
            a1 += p * sv[j][d2 + 1];
        }
        *reinterpret_cast<__half2*>(&g_attn[(base + i) * HIDDEN + h * HEAD_DIM + d2]) =
            __floats2half2_rn(a0, a1);
    }
}

// ---------------------------------------------------------------------------
extern "C" void kernel_launch(void* const* d_in, const int* in_sizes, int n_in,
                              void* d_out, int out_size) {
    const float* x    = (const float*)d_in[0];   // [4096,16,512]
    const float* wqkv = (const float*)d_in[1];   // [1536,512]
    const float* wo   = (const float*)d_in[2];   // [512,512]
    float* out        = (float*)d_out;           // [4096,16,512]

    f2h_x_kernel <<<(NTOK * HIDDEN) / 1024, 256>>>(x);
    f2h_wq_kernel<<<(NQKV * HIDDEN) / 1024, 256>>>(wqkv);
    f2h_wo_kernel<<<(HIDDEN * HIDDEN) / 1024, 256>>>(wo);

    {   // QKV: [65536,512] x [512,1536]
        dim3 grid(NQKV / 128, NTOK / 128);
        gemm_qkv_kernel<<<grid, 128>>>();
    }

    attn_kernel<<<BATCH * HEADS, 128>>>();

    {   // O-proj: [65536,512] x [512,512]
        dim3 grid(HIDDEN / 128, NTOK / 128);
        gemm_out_kernel<<<grid, 128>>>(out);
    }
}

// round 14
// speedup vs baseline: 1.0258x; 1.0258x over previous
#include <cuda_runtime.h>
#include <cuda_fp16.h>
#include <mma.h>
#include <cstdint>
#include <cstring>

using namespace nvcuda;

#define HIDDEN   512
#define HEADS    8
#define HEAD_DIM 64
#define BATCH    4096
#define SEQ      16
#define NTOK     (BATCH * SEQ)   // 65536
#define NQKV     (3 * HIDDEN)    // 1536

// ---- scratch (no allocs allowed; device globals are the sanctioned path) ----
__device__ __half g_wq  [(size_t)NQKV * HIDDEN];   // 1.5 MiB fp16 w_qkv
__device__ __half g_wo  [(size_t)HIDDEN * HIDDEN]; // 0.5 MiB fp16 w_o
__device__ __half g_qkvh[(size_t)NTOK * NQKV];     // 192 MiB fp16 qkv
__device__ __half g_attn[(size_t)NTOK * HIDDEN];   // 64 MiB  fp16 attn out

// ---------------------------------------------------------------------------
// cp.async helpers (LDGSTS, 16B)
// ---------------------------------------------------------------------------
__device__ __forceinline__ void cp_async16(void* smem, const void* gmem) {
    unsigned int s = (unsigned int)__cvta_generic_to_shared(smem);
    asm volatile("cp.async.cg.shared.global [%0], [%1], 16;\n" :: "r"(s), "l"(gmem));
}
__device__ __forceinline__ void cp_commit() {
    asm volatile("cp.async.commit_group;\n" ::: "memory");
}
template <int N>
__device__ __forceinline__ void cp_wait() {
    asm volatile("cp.async.wait_group %0;\n" :: "n"(N) : "memory");
}
__device__ __forceinline__ unsigned h2u(__half2 h) {
    unsigned u; memcpy(&u, &h, 4); return u;
}

// ---------------------------------------------------------------------------
// fp32 -> fp16 converters for the small weight tensors
// ---------------------------------------------------------------------------
__device__ __forceinline__ void f2h_body(const float* __restrict__ in,
                                         __half* __restrict__ out, int n) {
    int i = 4 * (blockIdx.x * blockDim.x + threadIdx.x);
    if (i < n) {
        float4 v = *reinterpret_cast<const float4*>(in + i);
        *reinterpret_cast<__half2*>(out + i)     = __floats2half2_rn(v.x, v.y);
        *reinterpret_cast<__half2*>(out + i + 2) = __floats2half2_rn(v.z, v.w);
    }
}
__global__ void f2h_wq_kernel(const float* __restrict__ in) { f2h_body(in, g_wq, NQKV * HIDDEN); }
__global__ void f2h_wo_kernel(const float* __restrict__ in) { f2h_body(in, g_wo, HIDDEN * HIDDEN); }

// ---------------------------------------------------------------------------
// QKV GEMM with fused A conversion:
//   C[M,N] = fp16(A_f32[M,K]) * B[N,K]^T,  fp32 accum, fp16 out.
// CTA tile 128x128x32, 128 threads = 4 warps, warp tile 64x64 (2x2 grid) —
// identical compute skeleton to the proven R7 kernel. A is loaded fp32 via
// LDG into registers (issued post-barrier, consumed post-MMA), converted,
// STS'd fp16; B staged via cp.async double buffering as before.
// ---------------------------------------------------------------------------
__global__ __launch_bounds__(128) void gemm_qkv_kernel(const float* __restrict__ Xf) {
    constexpr int BM = 128, BN = 128, BK = 32, LDS = BK + 8; // 40 halves = 80B rows
    constexpr int N = NQKV, K = HIDDEN;
    __shared__ __align__(16) __half As[2][BM * LDS];
    __shared__ __align__(16) __half Bs[2][BN * LDS];

    const int bm   = blockIdx.y * BM;
    const int bn   = blockIdx.x * BN;
    const int tid  = threadIdx.x;
    const int warp = tid >> 5;
    const int wm   = (warp & 1) * 64;    // warp row offset in tile
    const int wn   = (warp >> 1) * 64;   // warp col offset in tile

    // B stage loader: 128x32 halves = 512 int4, 4/thread (cp.async)
    auto load_B = [&](int kt, int buf) {
        #pragma unroll
        for (int l = 0; l < 4; l++) {
            int v  = tid + l * 128;
            int r  = v >> 2;
            int c8 = (v & 3) * 8;
            cp_async16(&Bs[buf][r * LDS + c8], &g_wq[(size_t)(bn + r) * K + kt + c8]);
        }
        cp_commit();
    };

    // A register pipeline: 128x32 floats per stage = 1024 float4, 8/thread
    float4 ar[8];
    auto ldg_A = [&](int kt) {
        #pragma unroll
        for (int l = 0; l < 4; l++) {
            int v  = tid + l * 128;
            int r  = v >> 2;
            int c8 = (v & 3) * 8;
            const float* src = &Xf[(size_t)(bm + r) * K + kt + c8];
            ar[2 * l]     = *reinterpret_cast<const float4*>(src);
            ar[2 * l + 1] = *reinterpret_cast<const float4*>(src + 4);
        }
    };
    auto sts_A = [&](int buf) {
        #pragma unroll
        for (int l = 0; l < 4; l++) {
            int v  = tid + l * 128;
            int r  = v >> 2;
            int c8 = (v & 3) * 8;
            uint4 w;
            w.x = h2u(__floats2half2_rn(ar[2 * l].x,     ar[2 * l].y));
            w.y = h2u(__floats2half2_rn(ar[2 * l].z,     ar[2 * l].w));
            w.z = h2u(__floats2half2_rn(ar[2 * l + 1].x, ar[2 * l + 1].y));
            w.w = h2u(__floats2half2_rn(ar[2 * l + 1].z, ar[2 * l + 1].w));
            *reinterpret_cast<uint4*>(&As[buf][r * LDS + c8]) = w;
        }
    };

    wmma::fragment<wmma::accumulator, 16, 16, 16, float> acc[4][4];
    #pragma unroll
    for (int i = 0; i < 4; i++)
        #pragma unroll
        for (int j = 0; j < 4; j++) wmma::fill_fragment(acc[i][j], 0.0f);

    const int nst = K / BK;   // 16
    // prologue: stage 0 fully staged before loop
    ldg_A(0);
    load_B(0, 0);
    sts_A(0);

    for (int s = 0; s < nst; s++) {
        cp_wait<0>();
        __syncthreads();           // stage s (A STS + B cp.async) visible to all
        if (s + 1 < nst) {
            load_B((s + 1) * BK, (s + 1) & 1);  // post-barrier: prior reads of that buf done
            ldg_A((s + 1) * BK);                // LDG latency covered by MMA below
        }

        const __half* as = As[s & 1];
        const __half* bs = Bs[s & 1];
        #pragma unroll
        for (int kk = 0; kk < BK; kk += 16) {
            wmma::fragment<wmma::matrix_a, 16, 16, 16, __half, wmma::row_major> af[4];
            wmma::fragment<wmma::matrix_b, 16, 16, 16, __half, wmma::col_major> bf[4];
            #pragma unroll
            for (int i = 0; i < 4; i++)
                wmma::load_matrix_sync(af[i], &as[(wm + i * 16) * LDS + kk], LDS);
            #pragma unroll
            for (int j = 0; j < 4; j++)
                wmma::load_matrix_sync(bf[j], &bs[(wn + j * 16) * LDS + kk], LDS);
            #pragma unroll
            for (int i = 0; i < 4; i++)
                #pragma unroll
                for (int j = 0; j < 4; j++)
                    wmma::mma_sync(acc[i][j], af[i], bf[j], acc[i][j]);
        }

        if (s + 1 < nst) sts_A((s + 1) & 1);   // after this stage's MMA; published at next barrier
    }

    #pragma unroll
    for (int i = 0; i < 4; i++) {
        #pragma unroll
        for (int j = 0; j < 4; j++) {
            wmma::fragment<wmma::accumulator, 16, 16, 16, __half> hf;
            #pragma unroll
            for (int e = 0; e < hf.num_elements; e++)
                hf.x[e] = __float2half(acc[i][j].x[e]);
            wmma::store_matrix_sync(&g_qkvh[(size_t)(bm + wm + i * 16) * N + bn + wn + j * 16],
                                    hf, N, wmma::mem_row_major);
        }
    }
}

// ---------------------------------------------------------------------------
// O-proj GEMM (fp16 A from g_attn, fp32 out) — unchanged R7 skeleton.
// ---------------------------------------------------------------------------
__global__ __launch_bounds__(128) void gemm_out_kernel(float* __restrict__ C) {
    constexpr int BM = 128, BN = 128, BK = 32, LDS = BK + 8;
    constexpr int N = HIDDEN, K = HIDDEN;
    __shared__ __align__(16) __half As[2][BM * LDS];
    __shared__ __align__(16) __half Bs[2][BN * LDS];

    const int bm   = blockIdx.y * BM;
    const int bn   = blockIdx.x * BN;
    const int tid  = threadIdx.x;
    const int warp = tid >> 5;
    const int wm   = (warp & 1) * 64;
    const int wn   = (warp >> 1) * 64;

    auto stage_load = [&](int kt, int buf) {
        #pragma unroll
        for (int l = 0; l < 4; l++) {
            int v  = tid + l * 128;
            int r  = v >> 2;
            int c8 = (v & 3) * 8;
            cp_async16(&As[buf][r * LDS + c8], &g_attn[(size_t)(bm + r) * K + kt + c8]);
            cp_async16(&Bs[buf][r * LDS + c8], &g_wo[(size_t)(bn + r) * K + kt + c8]);
        }
        cp_commit();
    };

    wmma::fragment<wmma::accumulator, 16, 16, 16, float> acc[4][4];
    #pragma unroll
    for (int i = 0; i < 4; i++)
        #pragma unroll
        for (int j = 0; j < 4; j++) wmma::fill_fragment(acc[i][j], 0.0f);

    const int nst = K / BK;
    stage_load(0, 0);

    for (int s = 0; s < nst; s++) {
        cp_wait<0>();
        __syncthreads();
        if (s + 1 < nst) stage_load((s + 1) * BK, (s + 1) & 1);

        const __half* as = As[s & 1];
        const __half* bs = Bs[s & 1];
        #pragma unroll
        for (int kk = 0; kk < BK; kk += 16) {
            wmma::fragment<wmma::matrix_a, 16, 16, 16, __half, wmma::row_major> af[4];
            wmma::fragment<wmma::matrix_b, 16, 16, 16, __half, wmma::col_major> bf[4];
            #pragma unroll
            for (int i = 0; i < 4; i++)
                wmma::load_matrix_sync(af[i], &as[(wm + i * 16) * LDS + kk], LDS);
            #pragma unroll
            for (int j = 0; j < 4; j++)
                wmma::load_matrix_sync(bf[j], &bs[(wn + j * 16) * LDS + kk], LDS);
            #pragma unroll
            for (int i = 0; i < 4; i++)
                #pragma unroll
                for (int j = 0; j < 4; j++)
                    wmma::mma_sync(acc[i][j], af[i], bf[j], acc[i][j]);
        }
    }

    #pragma unroll
    for (int i = 0; i < 4; i++)
        #pragma unroll
        for (int j = 0; j < 4; j++)
            wmma::store_matrix_sync(&C[(size_t)(bm + wm + i * 16) * N + bn + wn + j * 16],
                                    acc[i][j], N, wmma::mem_row_major);
}

// ---------------------------------------------------------------------------
// Attention: one block per (batch, head). fp16 qkv in, exact fp32 softmax,
// fp16 attn out in [token, h*64+d] layout.
// ---------------------------------------------------------------------------
__global__ __launch_bounds__(128) void attn_kernel() {
    const int b = blockIdx.x >> 3;
    const int h = blockIdx.x & 7;
    const size_t base = (size_t)b * SEQ;
    const int tid = threadIdx.x;

    __shared__ float sq[SEQ][68], sk[SEQ][68], sv[SEQ][68];
    __shared__ float sp[SEQ][SEQ + 1];

    #pragma unroll
    for (int l = 0; l < 3; l++) {
        int s  = tid >> 3;
        int d8 = (tid & 7) * 8;
        int4 raw = *reinterpret_cast<const int4*>(
            &g_qkvh[(base + s) * NQKV + l * HIDDEN + h * HEAD_DIM + d8]);
        const __half2* hp = reinterpret_cast<const __half2*>(&raw);
        float* dst = (l == 0) ? &sq[s][d8] : (l == 1) ? &sk[s][d8] : &sv[s][d8];
        #pragma unroll
        for (int p = 0; p < 4; p++) {
            float2 f = __half22float2(hp[p]);
            dst[2 * p]     = f.x;
            dst[2 * p + 1] = f.y;
        }
    }
    __syncthreads();

    #pragma unroll
    for (int l = 0; l < 2; l++) {
        int sidx = tid + l * 128;
        int i = sidx >> 4, j = sidx & 15;
        float a = 0.f;
        #pragma unroll
        for (int d = 0; d < HEAD_DIM; d++) a += sq[i][d] * sk[j][d];
        sp[i][j] = a * 0.125f;
    }
    __syncthreads();

    if (tid < SEQ) {
        float m = sp[tid][0];
        #pragma unroll
        for (int j = 1; j < SEQ; j++) m = fmaxf(m, sp[tid][j]);
        float e[SEQ], s = 0.f;
        #pragma unroll
        for (int j = 0; j < SEQ; j++) { e[j] = expf(sp[tid][j] - m); s += e[j]; }
        float inv = 1.0f / s;
        #pragma unroll
        for (int j = 0; j < SEQ; j++) sp[tid][j] = e[j] * inv;
    }
    __syncthreads();

    #pragma unroll
    for (int l = 0; l < 4; l++) {
        int o  = tid + l * 128;
        int i  = o >> 5;
        int d2 = (o & 31) * 2;
        float a0 = 0.f, a1 = 0.f;
        #pragma unroll
        for (int j = 0; j < SEQ; j++) {
            float p = sp[i][j];
            a0 += p * sv[j][d2];
            a1 += p * sv[j][d2 + 1];
        }
        *reinterpret_cast<__half2*>(&g_attn[(base + i) * HIDDEN + h * HEAD_DIM + d2]) =
            __floats2half2_rn(a0, a1);
    }
}

// ---------------------------------------------------------------------------
extern "C" void kernel_launch(void* const* d_in, const int* in_sizes, int n_in,
                              void* d_out, int out_size) {
    const float* x    = (const float*)d_in[0];   // [4096,16,512]
    const float* wqkv = (const float*)d_in[1];   // [1536,512]
    const float* wo   = (const float*)d_in[2];   // [512,512]
    float* out        = (float*)d_out;           // [4096,16,512]

    f2h_wq_kernel<<<(NQKV * HIDDEN) / 1024, 256>>>(wqkv);
    f2h_wo_kernel<<<(HIDDEN * HIDDEN) / 1024, 256>>>(wo);

    {   // QKV: [65536,512](fp32, fused convert) x [512,1536]
        dim3 grid(NQKV / 128, NTOK / 128);
        gemm_qkv_kernel<<<grid, 128>>>(x);
    }

    attn_kernel<<<BATCH * HEADS, 128>>>();

    {   // O-proj: [65536,512] x [512,512]
        dim3 grid(HIDDEN / 128, NTOK / 128);
        gemm_out_kernel<<<grid, 128>>>(out);
    }
}

// round 15
// speedup vs baseline: 1.1181x; 1.0900x over previous
#include <cuda_runtime.h>
#include <cuda_fp16.h>
#include <mma.h>
#include <cstdint>

using namespace nvcuda;

#define HIDDEN   512
#define HEADS    8
#define HEAD_DIM 64
#define BATCH    4096
#define SEQ      16
#define NTOK     (BATCH * SEQ)   // 65536
#define NQKV     (3 * HIDDEN)    // 1536

// ---- scratch (no allocs allowed; device globals are the sanctioned path) ----
__device__ __half g_xh  [(size_t)NTOK * HIDDEN];   // 64 MiB  fp16 input
__device__ __half g_wq  [(size_t)NQKV * HIDDEN];   // 1.5 MiB fp16 w_qkv
__device__ __half g_wo  [(size_t)HIDDEN * HIDDEN]; // 0.5 MiB fp16 w_o
__device__ __half g_qkvh[(size_t)NTOK * NQKV];     // 192 MiB fp16 qkv
__device__ __half g_attn[(size_t)NTOK * HIDDEN];   // 64 MiB  fp16 attn out

// ---------------------------------------------------------------------------
// cp.async helpers (LDGSTS, 16B)
// ---------------------------------------------------------------------------
__device__ __forceinline__ void cp_async16(void* smem, const void* gmem) {
    unsigned int s = (unsigned int)__cvta_generic_to_shared(smem);
    asm volatile("cp.async.cg.shared.global [%0], [%1], 16;\n" :: "r"(s), "l"(gmem));
}
__device__ __forceinline__ void cp_commit() {
    asm volatile("cp.async.commit_group;\n" ::: "memory");
}
template <int N>
__device__ __forceinline__ void cp_wait() {
    asm volatile("cp.async.wait_group %0;\n" :: "n"(N) : "memory");
}

// ---------------------------------------------------------------------------
// fp32 -> fp16 converters (n always multiple of 4)
// ---------------------------------------------------------------------------
__device__ __forceinline__ void f2h_body(const float* __restrict__ in,
                                         __half* __restrict__ out, int n) {
    int i = 4 * (blockIdx.x * blockDim.x + threadIdx.x);
    if (i < n) {
        float4 v = *reinterpret_cast<const float4*>(in + i);
        *reinterpret_cast<__half2*>(out + i)     = __floats2half2_rn(v.x, v.y);
        *reinterpret_cast<__half2*>(out + i + 2) = __floats2half2_rn(v.z, v.w);
    }
}
__global__ void f2h_x_kernel (const float* __restrict__ in) { f2h_body(in, g_xh, NTOK * HIDDEN); }
__global__ void f2h_wq_kernel(const float* __restrict__ in) { f2h_body(in, g_wq, NQKV * HIDDEN); }
__global__ void f2h_wo_kernel(const float* __restrict__ in) { f2h_body(in, g_wo, HIDDEN * HIDDEN); }

// ---------------------------------------------------------------------------
// GEMM: C[M,N] = A[M,K] * B[N,K]^T   (A,B fp16 K-contiguous; fp32 accum)
// CTA tile 128x128x32, 128 threads = 4 warps, warp tile 64x64 (2x2 grid).
// 2-stage cp.async double buffering. (Proven R7 kernel, 333us on QKV.)
// ---------------------------------------------------------------------------
template <bool HALF_OUT>
__device__ __forceinline__ void gemm_body(const __half* __restrict__ A,
                                          const __half* __restrict__ B,
                                          __half* __restrict__ Ch,
                                          float* __restrict__ Cf,
                                          int N, int K) {
    constexpr int BM = 128, BN = 128, BK = 32, LDS = BK + 8; // 40 halves = 80B rows
    __shared__ __align__(16) __half As[2][BM * LDS];
    __shared__ __align__(16) __half Bs[2][BN * LDS];

    const int bm   = blockIdx.y * BM;
    const int bn   = blockIdx.x * BN;
    const int tid  = threadIdx.x;
    const int warp = tid >> 5;
    const int wm   = (warp & 1) * 64;    // warp row offset in tile
    const int wn   = (warp >> 1) * 64;   // warp col offset in tile

    auto stage_load = [&](int kt, int buf) {
        #pragma unroll
        for (int l = 0; l < 4; l++) {
            int v  = tid + l * 128;
            int r  = v >> 2;
            int c8 = (v & 3) * 8;
            cp_async16(&As[buf][r * LDS + c8], &A[(size_t)(bm + r) * K + kt + c8]);
            cp_async16(&Bs[buf][r * LDS + c8], &B[(size_t)(bn + r) * K + kt + c8]);
        }
        cp_commit();
    };

    wmma::fragment<wmma::accumulator, 16, 16, 16, float> acc[4][4];
    #pragma unroll
    for (int i = 0; i < 4; i++)
        #pragma unroll
        for (int j = 0; j < 4; j++) wmma::fill_fragment(acc[i][j], 0.0f);

    const int nst = K / BK;
    stage_load(0, 0);

    for (int s = 0; s < nst; s++) {
        cp_wait<0>();
        __syncthreads();
        if (s + 1 < nst) stage_load((s + 1) * BK, (s + 1) & 1);

        const __half* as = As[s & 1];
        const __half* bs = Bs[s & 1];
        #pragma unroll
        for (int kk = 0; kk < BK; kk += 16) {
            wmma::fragment<wmma::matrix_a, 16, 16, 16, __half, wmma::row_major> af[4];
            wmma::fragment<wmma::matrix_b, 16, 16, 16, __half, wmma::col_major> bf[4];
            #pragma unroll
            for (int i = 0; i < 4; i++)
                wmma::load_matrix_sync(af[i], &as[(wm + i * 16) * LDS + kk], LDS);
            #pragma unroll
            for (int j = 0; j < 4; j++)
                wmma::load_matrix_sync(bf[j], &bs[(wn + j * 16) * LDS + kk], LDS);
            #pragma unroll
            for (int i = 0; i < 4; i++)
                #pragma unroll
                for (int j = 0; j < 4; j++)
                    wmma::mma_sync(acc[i][j], af[i], bf[j], acc[i][j]);
        }
    }

    #pragma unroll
    for (int i = 0; i < 4; i++) {
        #pragma unroll
        for (int j = 0; j < 4; j++) {
            if (HALF_OUT) {
                wmma::fragment<wmma::accumulator, 16, 16, 16, __half> hf;
                #pragma unroll
                for (int e = 0; e < hf.num_elements; e++)
                    hf.x[e] = __float2half(acc[i][j].x[e]);
                wmma::store_matrix_sync(&Ch[(size_t)(bm + wm + i * 16) * N + bn + wn + j * 16],
                                        hf, N, wmma::mem_row_major);
            } else {
                wmma::store_matrix_sync(&Cf[(size_t)(bm + wm + i * 16) * N + bn + wn + j * 16],
                                        acc[i][j], N, wmma::mem_row_major);
            }
        }
    }
}

__global__ __launch_bounds__(128) void gemm_qkv_kernel() {
    gemm_body<true>(g_xh, g_wq, g_qkvh, nullptr, NQKV, HIDDEN);
}
__global__ __launch_bounds__(128) void gemm_out_kernel(float* __restrict__ C) {
    gemm_body<false>(g_attn, g_wo, nullptr, C, HIDDEN, HIDDEN);
}

// ---------------------------------------------------------------------------
// Attention v2: one block per (batch, head). q/k/v kept fp16 in smem
// (68-half rows: word-stride 34 -> per-row bank shift 2, 16 rows cover 16
// distinct banks, 8B-aligned), all smem reads vectorized as uint2 (4 halves).
// fp32 accumulate + exact softmax -> numerics identical to before.
// ---------------------------------------------------------------------------
#define ALD 68   // padded row length in halves

__global__ __launch_bounds__(128) void attn_kernel() {
    const int b = blockIdx.x >> 3;
    const int h = blockIdx.x & 7;
    const size_t base = (size_t)b * SEQ;
    const int tid = threadIdx.x;

    __shared__ __half sq[SEQ][ALD], sk[SEQ][ALD], sv[SEQ][ALD];
    __shared__ float  sp[SEQ][SEQ + 1];

    // Load q,k,v fp16 -> fp16 smem: 3 int4 (8 halves) per thread.
    #pragma unroll
    for (int l = 0; l < 3; l++) {
        int s  = tid >> 3;
        int d8 = (tid & 7) * 8;
        int4 raw = *reinterpret_cast<const int4*>(
            &g_qkvh[(base + s) * NQKV + l * HIDDEN + h * HEAD_DIM + d8]);
        __half* dst = (l == 0) ? &sq[s][d8] : (l == 1) ? &sk[s][d8] : &sv[s][d8];
        const uint2* u = reinterpret_cast<const uint2*>(&raw);
        reinterpret_cast<uint2*>(dst)[0] = u[0];   // 8B stores: 136B rows are 8B-aligned
        reinterpret_cast<uint2*>(dst)[1] = u[1];
    }
    __syncthreads();

    // scores[i][j] = (q_i . k_j) / 8 -- 2 scores/thread, uint2 (4-half) loads
    #pragma unroll
    for (int l = 0; l < 2; l++) {
        int sidx = tid + l * 128;
        int i = sidx >> 4, j = sidx & 15;
        float a = 0.f;
        #pragma unroll
        for (int c = 0; c < 16; c++) {
            uint2 qu = *reinterpret_cast<const uint2*>(&sq[i][c * 4]);
            uint2 ku = *reinterpret_cast<const uint2*>(&sk[j][c * 4]);
            float2 q0 = __half22float2(*reinterpret_cast<const __half2*>(&qu.x));
            float2 q1 = __half22float2(*reinterpret_cast<const __half2*>(&qu.y));
            float2 k0 = __half22float2(*reinterpret_cast<const __half2*>(&ku.x));
            float2 k1 = __half22float2(*reinterpret_cast<const __half2*>(&ku.y));
            a += q0.x * k0.x + q0.y * k0.y + q1.x * k1.x + q1.y * k1.y;
        }
        sp[i][j] = a * 0.125f;
    }
    __syncthreads();

    // softmax per row (16 threads)
    if (tid < SEQ) {
        float m = sp[tid][0];
        #pragma unroll
        for (int j = 1; j < SEQ; j++) m = fmaxf(m, sp[tid][j]);
        float e[SEQ], s = 0.f;
        #pragma unroll
        for (int j = 0; j < SEQ; j++) { e[j] = expf(sp[tid][j] - m); s += e[j]; }
        float inv = 1.0f / s;
        #pragma unroll
        for (int j = 0; j < SEQ; j++) sp[tid][j] = e[j] * inv;
    }
    __syncthreads();

    // out[i][c4..c4+3] = sum_j p[i][j] * v[j][c4..c4+3] -- 2 items/thread
    #pragma unroll
    for (int l = 0; l < 2; l++) {
        int o  = tid + l * 128;          // 0..255
        int i  = o >> 4;                 // row 0..15
        int c4 = (o & 15) * 4;           // col base 0..60
        float a0 = 0.f, a1 = 0.f, a2 = 0.f, a3 = 0.f;
        #pragma unroll
        for (int j = 0; j < SEQ; j++) {
            float p = sp[i][j];
            uint2 vu = *reinterpret_cast<const uint2*>(&sv[j][c4]);
            float2 v0 = __half22float2(*reinterpret_cast<const __half2*>(&vu.x));
            float2 v1 = __half22float2(*reinterpret_cast<const __half2*>(&vu.y));
            a0 += p * v0.x; a1 += p * v0.y; a2 += p * v1.x; a3 += p * v1.y;
        }
        uint2 w;
        *reinterpret_cast<__half2*>(&w.x) = __floats2half2_rn(a0, a1);
        *reinterpret_cast<__half2*>(&w.y) = __floats2half2_rn(a2, a3);
        *reinterpret_cast<uint2*>(&g_attn[(base + i) * HIDDEN + h * HEAD_DIM + c4]) = w;
    }
}

// ---------------------------------------------------------------------------
extern "C" void kernel_launch(void* const* d_in, const int* in_sizes, int n_in,
                              void* d_out, int out_size) {
    const float* x    = (const float*)d_in[0];   // [4096,16,512]
    const float* wqkv = (const float*)d_in[1];   // [1536,512]
    const float* wo   = (const float*)d_in[2];   // [512,512]
    float* out        = (float*)d_out;           // [4096,16,512]

    f2h_x_kernel <<<(NTOK * HIDDEN) / 1024, 256>>>(x);
    f2h_wq_kernel<<<(NQKV * HIDDEN) / 1024, 256>>>(wqkv);
    f2h_wo_kernel<<<(HIDDEN * HIDDEN) / 1024, 256>>>(wo);

    {   // QKV: [65536,512] x [512,1536]
        dim3 grid(NQKV / 128, NTOK / 128);
        gemm_qkv_kernel<<<grid, 128>>>();
    }

    attn_kernel<<<BATCH * HEADS, 128>>>();

    {   // O-proj: [65536,512] x [512,512]
        dim3 grid(HIDDEN / 128, NTOK / 128);
        gemm_out_kernel<<<grid, 128>>>(out);
    }
}